// round 6
// baseline (speedup 1.0000x reference)
#include <cuda_runtime.h>
#include <cuda_bf16.h>
#include <cstdint>
#include <math.h>

// Problem constants
#define T_SEQ   2048
#define C_EMB   1024
#define QKV_DIM 1536
#define N_HEAD  16
#define N_GRP   4
#define HEAD_D  64

// Scratch (allocation-free: __device__ globals)
__device__ float g_x [T_SEQ * C_EMB];             // tf32-rounded x
__device__ float g_wa[C_EMB * QKV_DIM];           // tf32-rounded w_attn
__device__ float g_wp[C_EMB * C_EMB];             // tf32-rounded w_proj
__device__ float g_Q[N_HEAD * T_SEQ * HEAD_D];    // rounded, pre-scaled 1/8
__device__ float g_K[N_GRP * T_SEQ * HEAD_D];     // rounded
__device__ float g_V[N_GRP * T_SEQ * HEAD_D];     // rounded
__device__ float g_Y[T_SEQ * C_EMB];              // rounded
__device__ float2 g_rope[T_SEQ * (HEAD_D / 2)];   // (cos, sin) table

// ---------------------------------------------------------------------------
// helpers
// ---------------------------------------------------------------------------
__device__ __forceinline__ unsigned f2tf(float x) {
    unsigned r;
    asm("cvt.rna.tf32.f32 %0, %1;" : "=r"(r) : "f"(x));
    return r;
}
__device__ __forceinline__ float ftf(float x) {
    return __uint_as_float(f2tf(x));
}

__device__ __forceinline__ void mma_tf32(float c[4], const unsigned a[4],
                                         unsigned b0, unsigned b1) {
    asm volatile(
        "mma.sync.aligned.m16n8k8.row.col.f32.tf32.tf32.f32 "
        "{%0,%1,%2,%3}, {%4,%5,%6,%7}, {%8,%9}, {%0,%1,%2,%3};\n"
        : "+f"(c[0]), "+f"(c[1]), "+f"(c[2]), "+f"(c[3])
        : "r"(a[0]), "r"(a[1]), "r"(a[2]), "r"(a[3]), "r"(b0), "r"(b1));
}

__device__ __forceinline__ void cp16(uint32_t dst_smem, const void* src) {
    asm volatile("cp.async.cg.shared.global [%0], [%1], 16;\n"
                 :: "r"(dst_smem), "l"(src));
}
__device__ __forceinline__ void cp_commit() {
    asm volatile("cp.async.commit_group;\n");
}
template <int N>
__device__ __forceinline__ void cp_wait() {
    asm volatile("cp.async.wait_group %0;\n" :: "n"(N));
}

// ---------------------------------------------------------------------------
// Pre-round to tf32 (elementwise)
// ---------------------------------------------------------------------------
__global__ void round_tf32(const float* __restrict__ in,
                           float* __restrict__ out, int n)
{
    int i = (blockIdx.x * blockDim.x + threadIdx.x) * 4;
    if (i >= n) return;
    float4 v = *(const float4*)(in + i);
    v.x = ftf(v.x); v.y = ftf(v.y); v.z = ftf(v.z); v.w = ftf(v.w);
    *(float4*)(out + i) = v;
}

// ---------------------------------------------------------------------------
// RoPE cos/sin table: g_rope[t*32 + i] = (cos, sin) of t * theta^{-2i/64}
// ---------------------------------------------------------------------------
__global__ void build_rope()
{
    int idx = blockIdx.x * blockDim.x + threadIdx.x;
    if (idx >= T_SEQ * 32) return;
    int t = idx >> 5;
    int i = idx & 31;
    float inv = powf(10000.0f, -2.0f * (float)i / (float)HEAD_D);
    float ang = (float)t * inv;
    float s, c;
    sincosf(ang, &s, &c);
    g_rope[idx] = make_float2(c, s);
}

// ---------------------------------------------------------------------------
// tf32 tensor-core GEMM, 3-stage cp.async pipeline.
// Block tile 64x128, 8 warps (2Mx4N), warp tile 32x32, K-step 16.
// mode 0: C[M,N] = A @ B (plain store)
// mode 1: QKV epilogue — apply RoPE and scatter to g_Q (x1/8), g_K, g_V.
// ---------------------------------------------------------------------------
#define AS_STRIDE 20
#define BS_STRIDE 136
#define A_WORDS   (64 * AS_STRIDE)           // 1280
#define B_WORDS   (16 * BS_STRIDE)           // 2176
#define STAGE_WORDS (A_WORDS + B_WORDS)      // 3456
#define GEMM_SMEM (3 * STAGE_WORDS * 4)      // 41472 B

__device__ __forceinline__ void gemm_load_stage(
    uint32_t sbase, const float* A, const float* B,
    int m0, int n0, int k0, int K, int N, int tid)
{
    uint32_t as = sbase;
    uint32_t bs = sbase + A_WORDS * 4;
    {
        int row = tid >> 2, kc = (tid & 3) * 4;
        cp16(as + (row * AS_STRIDE + kc) * 4,
             A + (size_t)(m0 + row) * K + k0 + kc);
    }
    #pragma unroll
    for (int i = 0; i < 2; i++) {
        int f = tid + i * 256;
        int r = f >> 5, c = (f & 31) * 4;
        cp16(bs + (r * BS_STRIDE + c) * 4,
             B + (size_t)(k0 + r) * N + n0 + c);
    }
}

__global__ __launch_bounds__(256) void gemm_tf32(
    const float* __restrict__ A, const float* __restrict__ B,
    float* __restrict__ C, int M, int N, int K, int mode)
{
    extern __shared__ float sm[];
    const uint32_t smem_u32 = (uint32_t)__cvta_generic_to_shared(sm);

    const int tid  = threadIdx.x;
    const int wid  = tid >> 5;
    const int lane = tid & 31;
    const int g    = lane >> 2;
    const int t    = lane & 3;
    const int wm   = wid & 1;
    const int wn   = wid >> 1;
    const int m0   = blockIdx.y * 64;
    const int n0   = blockIdx.x * 128;

    float acc[2][4][4];
    #pragma unroll
    for (int mt = 0; mt < 2; mt++)
        #pragma unroll
        for (int nt = 0; nt < 4; nt++)
            #pragma unroll
            for (int i = 0; i < 4; i++) acc[mt][nt][i] = 0.0f;

    gemm_load_stage(smem_u32, A, B, m0, n0, 0, K, N, tid);
    cp_commit();
    gemm_load_stage(smem_u32 + STAGE_WORDS * 4, A, B, m0, n0, 16, K, N, tid);
    cp_commit();

    int s = 0;
    for (int k0 = 0; k0 < K; k0 += 16) {
        cp_wait<1>();
        __syncthreads();
        if (k0 + 32 < K) {
            int s2 = s + 2; if (s2 >= 3) s2 -= 3;
            gemm_load_stage(smem_u32 + s2 * STAGE_WORDS * 4,
                            A, B, m0, n0, k0 + 32, K, N, tid);
        }
        cp_commit();

        const float* As_s = sm + s * STAGE_WORDS;
        const float* Bs_s = As_s + A_WORDS;
        #pragma unroll
        for (int kk = 0; kk < 2; kk++) {
            const int k8 = kk * 8;
            unsigned a[2][4];
            #pragma unroll
            for (int mt = 0; mt < 2; mt++) {
                int mb = wm * 32 + mt * 16;
                a[mt][0] = __float_as_uint(As_s[(mb + g    ) * AS_STRIDE + k8 + t    ]);
                a[mt][1] = __float_as_uint(As_s[(mb + g + 8) * AS_STRIDE + k8 + t    ]);
                a[mt][2] = __float_as_uint(As_s[(mb + g    ) * AS_STRIDE + k8 + t + 4]);
                a[mt][3] = __float_as_uint(As_s[(mb + g + 8) * AS_STRIDE + k8 + t + 4]);
            }
            #pragma unroll
            for (int nt = 0; nt < 4; nt++) {
                int nb = wn * 32 + nt * 8;
                unsigned b0 = __float_as_uint(Bs_s[(k8 + t    ) * BS_STRIDE + nb + g]);
                unsigned b1 = __float_as_uint(Bs_s[(k8 + t + 4) * BS_STRIDE + nb + g]);
                #pragma unroll
                for (int mt = 0; mt < 2; mt++)
                    mma_tf32(acc[mt][nt], a[mt], b0, b1);
            }
        }
        s++; if (s >= 3) s -= 3;
    }

    if (mode == 0) {
        #pragma unroll
        for (int mt = 0; mt < 2; mt++) {
            int r0 = m0 + wm * 32 + mt * 16 + g;
            #pragma unroll
            for (int nt = 0; nt < 4; nt++) {
                int c0 = n0 + wn * 32 + nt * 8 + 2 * t;
                *(float2*)&C[(size_t)r0 * N + c0] =
                    make_float2(acc[mt][nt][0], acc[mt][nt][1]);
                *(float2*)&C[(size_t)(r0 + 8) * N + c0] =
                    make_float2(acc[mt][nt][2], acc[mt][nt][3]);
            }
        }
    } else {
        // QKV epilogue: RoPE + split. Pair (c0, c0+1) is a rotation pair.
        // slot/group are warp-uniform (32-col warp span never crosses 64-col head).
        #pragma unroll
        for (int mt = 0; mt < 2; mt++) {
            int r0 = m0 + wm * 32 + mt * 16 + g;
            int r1 = r0 + 8;
            #pragma unroll
            for (int nt = 0; nt < 4; nt++) {
                int c0 = n0 + wn * 32 + nt * 8 + 2 * t;
                int gq   = c0 / (6 * HEAD_D);
                int w_   = c0 - gq * (6 * HEAD_D);
                int slot = w_ >> 6;          // 0..3 q, 4 k, 5 v
                int d    = w_ & 63;          // even
                int i    = d >> 1;

                float x0a = acc[mt][nt][0], x1a = acc[mt][nt][1];  // row r0
                float x0b = acc[mt][nt][2], x1b = acc[mt][nt][3];  // row r1

                if (slot < 5) {
                    float2 cs0 = g_rope[r0 * 32 + i];
                    float2 cs1 = g_rope[r1 * 32 + i];
                    float y0a = x0a * cs0.x - x1a * cs0.y;
                    float y1a = x1a * cs0.x + x0a * cs0.y;
                    float y0b = x0b * cs1.x - x1b * cs1.y;
                    float y1b = x1b * cs1.x + x0b * cs1.y;
                    x0a = y0a; x1a = y1a; x0b = y0b; x1b = y1b;
                }

                if (slot < 4) {
                    int h = gq * 4 + slot;
                    float* dst = g_Q + (size_t)h * T_SEQ * HEAD_D + d;
                    *(float2*)(dst + (size_t)r0 * HEAD_D) =
                        make_float2(ftf(x0a * 0.125f), ftf(x1a * 0.125f));
                    *(float2*)(dst + (size_t)r1 * HEAD_D) =
                        make_float2(ftf(x0b * 0.125f), ftf(x1b * 0.125f));
                } else if (slot == 4) {
                    float* dst = g_K + (size_t)gq * T_SEQ * HEAD_D + d;
                    *(float2*)(dst + (size_t)r0 * HEAD_D) =
                        make_float2(ftf(x0a), ftf(x1a));
                    *(float2*)(dst + (size_t)r1 * HEAD_D) =
                        make_float2(ftf(x0b), ftf(x1b));
                } else {
                    float* dst = g_V + (size_t)gq * T_SEQ * HEAD_D + d;
                    *(float2*)(dst + (size_t)r0 * HEAD_D) =
                        make_float2(ftf(x0a), ftf(x1a));
                    *(float2*)(dst + (size_t)r1 * HEAD_D) =
                        make_float2(ftf(x0b), ftf(x1b));
                }
            }
        }
    }
}

// ---------------------------------------------------------------------------
// Flash-style causal attention, tf32 mma, 2-buffer cp.async K/V pipeline.
// Block = 256 threads (8 warps), 128 queries/block, one head.
// Each warp owns 16 query rows; K/V tiles (64 keys) shared by all warps.
// LPT scheduling: heaviest q-tiles first. Per-warp skip of fully-masked tiles.
// ---------------------------------------------------------------------------
#define KS_STRIDE 68
#define VS_STRIDE 72
#define PS_STRIDE 68
#define K_WORDS (64 * KS_STRIDE)                 // 4352
#define V_WORDS (64 * VS_STRIDE)                 // 4608
#define P_WORDS (128 * PS_STRIDE)                // 8704
#define ATTN_SMEM ((2 * K_WORDS + 2 * V_WORDS + P_WORDS) * 4)   // 106496 B

__device__ __forceinline__ void attn_load_tile(
    uint32_t kbuf, uint32_t vbuf,
    const float* Kg, const float* Vg, int tid)
{
    #pragma unroll
    for (int i = 0; i < 4; i++) {
        int f = tid + i * 256;
        int row = f >> 4;
        int c = (f & 15) * 4;
        cp16(kbuf + (row * KS_STRIDE + c) * 4, Kg + (size_t)row * HEAD_D + c);
        cp16(vbuf + (row * VS_STRIDE + c) * 4, Vg + (size_t)row * HEAD_D + c);
    }
}

__global__ __launch_bounds__(256, 2) void attn_kernel()
{
    extern __shared__ float sm[];
    float* Kb[2] = { sm, sm + K_WORDS };
    float* Vb[2] = { sm + 2 * K_WORDS, sm + 2 * K_WORDS + V_WORDS };
    float* Ps   = sm + 2 * K_WORDS + 2 * V_WORDS;
    const uint32_t su = (uint32_t)__cvta_generic_to_shared(sm);
    const uint32_t kbu[2] = { su, su + K_WORDS * 4 };
    const uint32_t vbu[2] = { su + 2 * K_WORDS * 4, su + (2 * K_WORDS + V_WORDS) * 4 };

    const int h    = blockIdx.x;
    const int qt   = gridDim.y - 1 - blockIdx.y;   // LPT: heavy tiles first
    const int tid  = threadIdx.x;
    const int w    = tid >> 5;
    const int lane = tid & 31;
    const int g    = lane >> 2;
    const int t    = lane & 3;
    const int grp  = h >> 2;
    const int qw0  = qt * 128 + w * 16;            // warp's first query row

    const float* Kg = g_K + (size_t)grp * T_SEQ * HEAD_D;
    const float* Vg = g_V + (size_t)grp * T_SEQ * HEAD_D;

    // Q fragments (pre-rounded, pre-scaled in gmem)
    unsigned qa[8][4];
    {
        const float* Qb = g_Q + ((size_t)h * T_SEQ + qw0) * HEAD_D;
        #pragma unroll
        for (int ks = 0; ks < 8; ks++) {
            qa[ks][0] = __float_as_uint(Qb[(size_t)(g    ) * HEAD_D + ks * 8 + t    ]);
            qa[ks][1] = __float_as_uint(Qb[(size_t)(g + 8) * HEAD_D + ks * 8 + t    ]);
            qa[ks][2] = __float_as_uint(Qb[(size_t)(g    ) * HEAD_D + ks * 8 + t + 4]);
            qa[ks][3] = __float_as_uint(Qb[(size_t)(g + 8) * HEAD_D + ks * 8 + t + 4]);
        }
    }

    float oc[8][4];
    #pragma unroll
    for (int nt = 0; nt < 8; nt++)
        #pragma unroll
        for (int i = 0; i < 4; i++) oc[nt][i] = 0.0f;
    float l0 = 0.0f, l1 = 0.0f;

    attn_load_tile(kbu[0], vbu[0], Kg, Vg, tid);
    cp_commit();

    const int ntiles = 2 * qt + 2;    // k-tiles of 64 covering 0..qt*128+127
    int buf = 0;
    for (int kt = 0; kt < ntiles; kt++) {
        const int kbase = kt * 64;
        cp_wait<0>();
        __syncthreads();
        if (kt + 1 < ntiles) {
            attn_load_tile(kbu[buf ^ 1], vbu[buf ^ 1],
                           Kg + (size_t)(kbase + 64) * HEAD_D,
                           Vg + (size_t)(kbase + 64) * HEAD_D, tid);
        }
        cp_commit();

        // warp's rows are [qw0, qw0+15]; tile fully masked if kbase > qw0+15
        if (kbase <= qw0 + 15) {
            const float* Ks = Kb[buf];
            const float* Vs = Vb[buf];

            // S = Q @ K^T
            float sc[8][4];
            #pragma unroll
            for (int nt = 0; nt < 8; nt++)
                #pragma unroll
                for (int i = 0; i < 4; i++) sc[nt][i] = 0.0f;

            #pragma unroll
            for (int ks = 0; ks < 8; ks++) {
                #pragma unroll
                for (int nt = 0; nt < 8; nt++) {
                    unsigned b0 = __float_as_uint(Ks[(nt * 8 + g) * KS_STRIDE + ks * 8 + t    ]);
                    unsigned b1 = __float_as_uint(Ks[(nt * 8 + g) * KS_STRIDE + ks * 8 + t + 4]);
                    mma_tf32(sc[nt], qa[ks], b0, b1);
                }
            }

            // exp (+causal mask where tile overlaps the diagonal)
            const bool diag = (kbase + 63 > qw0);
            #pragma unroll
            for (int nt = 0; nt < 8; nt++) {
                int k0 = kbase + nt * 8 + 2 * t;
                float p0 = __expf(sc[nt][0]);
                float p1 = __expf(sc[nt][1]);
                float p2 = __expf(sc[nt][2]);
                float p3 = __expf(sc[nt][3]);
                if (diag) {
                    int q0 = qw0 + g, q1 = qw0 + g + 8;
                    if (k0     > q0) p0 = 0.0f;
                    if (k0 + 1 > q0) p1 = 0.0f;
                    if (k0     > q1) p2 = 0.0f;
                    if (k0 + 1 > q1) p3 = 0.0f;
                }
                l0 += p0 + p1;
                l1 += p2 + p3;
                int c = nt * 8 + 2 * t;
                Ps[(w * 16 + g    ) * PS_STRIDE + c    ] = ftf(p0);
                Ps[(w * 16 + g    ) * PS_STRIDE + c + 1] = ftf(p1);
                Ps[(w * 16 + g + 8) * PS_STRIDE + c    ] = ftf(p2);
                Ps[(w * 16 + g + 8) * PS_STRIDE + c + 1] = ftf(p3);
            }
            __syncwarp();   // Ps slab is warp-private

            // O += P @ V
            #pragma unroll
            for (int ks = 0; ks < 8; ks++) {
                unsigned pa[4];
                pa[0] = __float_as_uint(Ps[(w * 16 + g    ) * PS_STRIDE + ks * 8 + t    ]);
                pa[1] = __float_as_uint(Ps[(w * 16 + g + 8) * PS_STRIDE + ks * 8 + t    ]);
                pa[2] = __float_as_uint(Ps[(w * 16 + g    ) * PS_STRIDE + ks * 8 + t + 4]);
                pa[3] = __float_as_uint(Ps[(w * 16 + g + 8) * PS_STRIDE + ks * 8 + t + 4]);
                #pragma unroll
                for (int nt = 0; nt < 8; nt++) {
                    unsigned b0 = __float_as_uint(Vs[(ks * 8 + t    ) * VS_STRIDE + nt * 8 + g]);
                    unsigned b1 = __float_as_uint(Vs[(ks * 8 + t + 4) * VS_STRIDE + nt * 8 + g]);
                    mma_tf32(oc[nt], pa, b0, b1);
                }
            }
        }
        buf ^= 1;
    }

    l0 += __shfl_xor_sync(0xffffffff, l0, 1);
    l0 += __shfl_xor_sync(0xffffffff, l0, 2);
    l1 += __shfl_xor_sync(0xffffffff, l1, 1);
    l1 += __shfl_xor_sync(0xffffffff, l1, 2);
    float inv0 = 1.0f / l0;
    float inv1 = 1.0f / l1;

    float* Y0 = g_Y + (size_t)(qw0 + g    ) * C_EMB + h * HEAD_D;
    float* Y1 = g_Y + (size_t)(qw0 + g + 8) * C_EMB + h * HEAD_D;
    #pragma unroll
    for (int nt = 0; nt < 8; nt++) {
        int c = nt * 8 + 2 * t;
        *(float2*)(Y0 + c) = make_float2(ftf(oc[nt][0] * inv0), ftf(oc[nt][1] * inv0));
        *(float2*)(Y1 + c) = make_float2(ftf(oc[nt][2] * inv1), ftf(oc[nt][3] * inv1));
    }
}

// ---------------------------------------------------------------------------
extern "C" void kernel_launch(void* const* d_in, const int* in_sizes, int n_in,
                              void* d_out, int out_size)
{
    const float* x      = (const float*)d_in[0];   // [1,2048,1024]
    const float* w_attn = (const float*)d_in[1];   // [1024,1536]
    const float* w_proj = (const float*)d_in[2];   // [1024,1024]
    float* out = (float*)d_out;                    // [1,2048,1024]

    float *xr, *war, *wpr, *Y;
    cudaGetSymbolAddress((void**)&xr,  g_x);
    cudaGetSymbolAddress((void**)&war, g_wa);
    cudaGetSymbolAddress((void**)&wpr, g_wp);
    cudaGetSymbolAddress((void**)&Y,   g_Y);

    cudaFuncSetAttribute(gemm_tf32,
                         cudaFuncAttributeMaxDynamicSharedMemorySize, GEMM_SMEM);
    cudaFuncSetAttribute(attn_kernel,
                         cudaFuncAttributeMaxDynamicSharedMemorySize, ATTN_SMEM);

    // 0) pre-round inputs to tf32 + RoPE table
    {
        int n1 = T_SEQ * C_EMB, n2 = C_EMB * QKV_DIM, n3 = C_EMB * C_EMB;
        round_tf32<<<(n1 / 4 + 255) / 256, 256>>>(x, xr, n1);
        round_tf32<<<(n2 / 4 + 255) / 256, 256>>>(w_attn, war, n2);
        round_tf32<<<(n3 / 4 + 255) / 256, 256>>>(w_proj, wpr, n3);
        build_rope<<<(T_SEQ * 32 + 255) / 256, 256>>>();
    }
    // 1) QKV GEMM fused with RoPE + split (writes g_Q/g_K/g_V directly)
    {
        dim3 grid(QKV_DIM / 128, T_SEQ / 64);
        gemm_tf32<<<grid, 256, GEMM_SMEM>>>(xr, war, nullptr,
                                            T_SEQ, QKV_DIM, C_EMB, 1);
    }
    // 2) attention (256 thr, 128 queries/CTA, LPT)
    {
        dim3 grid(N_HEAD, T_SEQ / 128);
        attn_kernel<<<grid, 256, ATTN_SMEM>>>();
    }
    // 3) out = Y @ w_proj
    {
        dim3 grid(C_EMB / 128, T_SEQ / 64);
        gemm_tf32<<<grid, 256, GEMM_SMEM>>>(Y, wpr, out,
                                            T_SEQ, C_EMB, C_EMB, 0);
    }
}